// round 11
// baseline (speedup 1.0000x reference)
#include <cuda_runtime.h>
#include <cuda_bf16.h>

#define F_FEAT 16
#define D_IN   4
#define H      32
#define B_TOT  1024
#define T_MAX  512
#define PF_DIST 8       // prefetch distance in timesteps (one 128B line)

typedef unsigned long long ull;

__device__ float g_hT[B_TOT * F_FEAT * H];      // [b][f][h]  == h_cat[b][f*H+h]
__device__ float g_WT[F_FEAT * H * H];          // W_sq transposed
__device__ int   g_perm[B_TOT];                 // batches sorted by len, descending

// HW tanh (MUFU.TANH): single op; verified end-to-end rel_err ~8e-8.
__device__ __forceinline__ float mufu_tanh(float x) {
    float y; asm("tanh.approx.f32 %0, %1;" : "=f"(y) : "f"(x)); return y;
}
__device__ __forceinline__ float fast_sigmoid(float v) {
    return fmaf(0.5f, mufu_tanh(0.5f * v), 0.5f);
}
__device__ __forceinline__ float precise_sigmoid(float v) {
    return __fdividef(1.f, 1.f + __expf(-v));
}
__device__ __forceinline__ ull pack2(float lo, float hi) {
    ull d; asm("mov.b64 %0, {%1, %2};" : "=l"(d) : "f"(lo), "f"(hi)); return d;
}
__device__ __forceinline__ void unpack2(ull v, float& lo, float& hi) {
    asm("mov.b64 {%0, %1}, %2;" : "=f"(lo), "=f"(hi) : "l"(v));
}
__device__ __forceinline__ ull fma2(ull a, ull b, ull c) {
    ull d; asm("fma.rn.f32x2 %0, %1, %2, %3;" : "=l"(d) : "l"(a), "l"(b), "l"(c)); return d;
}
__device__ __forceinline__ ull add2(ull a, ull b) {
    ull d; asm("add.rn.f32x2 %0, %1, %2;" : "=l"(d) : "l"(a), "l"(b)); return d;
}
__device__ __forceinline__ float hsum2(ull v) {
    float lo, hi; unpack2(v, lo, hi); return lo + hi;
}
__device__ __forceinline__ void prefetch_l1(const void* p) {
    asm volatile("prefetch.global.L1 [%0];" :: "l"(p));
}

// Rank-sort batches by length (descending, stable). O(B^2) but tiny (~5us).
__global__ void sort_lens(const int* __restrict__ lens) {
    int b = blockIdx.x * blockDim.x + threadIdx.x;
    if (b >= B_TOT) return;
    int L = lens[b];
    int r = 0;
    for (int j = 0; j < B_TOT; j++) {
        int Lj = __ldg(lens + j);
        r += (Lj < L) || (Lj == L && j < b);
    }
    g_perm[B_TOT - 1 - r] = b;   // descending: longest first
}

// One warp per (feature, batch-PAIR). Decoupled ih/hh chains: hh starts the
// instant h lands from smem; ih runs when x arrives (deep-prefetched L1 hit);
// merged per gate with one add.f32x2. x is fully off the recurrence path.
__global__ void __launch_bounds__(128, 3) gru_kernel(
    const float* __restrict__ input,   // [B, F, T, D]
    const int*   __restrict__ lens,    // [B]
    const float* __restrict__ W_ih,    // [F, 3H, D]
    const float* __restrict__ W_hh,    // [F, 3H, H]
    const float* __restrict__ b_ih,    // [F, 3H]
    const float* __restrict__ b_hh)    // [F, 3H]
{
    __shared__ float hbuf[4][2][2][H];    // [warp][buffer][batch-slot][k]

    const int lane = threadIdx.x & 31;
    const int warp = threadIdx.x >> 5;
    const int pair = blockIdx.x;                 // 0..511, longest pairs first
    const int f    = blockIdx.y * 4 + warp;

    const int b0 = __ldg(g_perm + 2 * pair);         // longer
    const int b1 = __ldg(g_perm + 2 * pair + 1);     // shorter (or equal)
    const int L0 = __ldg(lens + b0);                 // loop bound (max)
    const int L1 = __ldg(lens + b1);

    // --- recurrent weights, packed along k as (W[2q], W[2q+1]) pairs ---
    const float* Whh = W_hh + f * (3 * H) * H;
    ull Wr2[H/2], Wz2[H/2], Wn2[H/2];
    {
        const float4* r4 = (const float4*)(Whh + lane * H);
        const float4* z4 = (const float4*)(Whh + (H + lane) * H);
        const float4* n4 = (const float4*)(Whh + (2 * H + lane) * H);
        #pragma unroll
        for (int q = 0; q < H / 4; q++) {
            float4 a = __ldg(r4 + q);
            Wr2[2*q] = pack2(a.x, a.y);  Wr2[2*q+1] = pack2(a.z, a.w);
            float4 c = __ldg(z4 + q);
            Wz2[2*q] = pack2(c.x, c.y);  Wz2[2*q+1] = pack2(c.z, c.w);
            float4 d = __ldg(n4 + q);
            Wn2[2*q] = pack2(d.x, d.y);  Wn2[2*q+1] = pack2(d.z, d.w);
        }
    }

    // input weights, packed along d
    const float* Wih = W_ih + f * (3 * H) * D_IN;
    const float4 wir = __ldg((const float4*)Wih + lane);
    const float4 wiz = __ldg((const float4*)Wih + H + lane);
    const float4 win = __ldg((const float4*)Wih + 2 * H + lane);
    const ull Wir01 = pack2(wir.x, wir.y), Wir23 = pack2(wir.z, wir.w);
    const ull Wiz01 = pack2(wiz.x, wiz.y), Wiz23 = pack2(wiz.z, wiz.w);
    const ull Win01 = pack2(win.x, win.y), Win23 = pack2(win.z, win.w);

    const float br  = __ldg(b_ih + f * 3 * H + lane)     + __ldg(b_hh + f * 3 * H + lane);
    const float bz  = __ldg(b_ih + f * 3 * H + H + lane) + __ldg(b_hh + f * 3 * H + H + lane);
    const float bin = __ldg(b_ih + f * 3 * H + 2 * H + lane);
    const float bhn = __ldg(b_hh + f * 3 * H + 2 * H + lane);
    const ull  bias_r = pack2(br, 0.f), bias_z = pack2(bz, 0.f);
    const ull  bias_in = pack2(bin, 0.f), bias_hn = pack2(bhn, 0.f);

    const float4* xp0 = (const float4*)input + ((size_t)b0 * F_FEAT + f) * T_MAX;
    const float4* xp1 = (const float4*)input + ((size_t)b1 * F_FEAT + f) * T_MAX;

    // warm L1 for the first PF_DIST steps of both streams
    #pragma unroll
    for (int w = 0; w < PF_DIST; w += 2) {   // 128B line granularity
        prefetch_l1(xp0 + min(w, L0 - 1));
        prefetch_l1(xp1 + min(w, L0 - 1));
    }

    float h0 = 0.f, h1 = 0.f;
    hbuf[warp][0][0][lane] = 0.f;
    hbuf[warp][0][1][lane] = 0.f;
    __syncwarp();
    int p = 0;

    for (int t = 0; t < L0; t++) {
        // x for THIS step (L1-hit thanks to deep prefetch) + prefetch ahead
        float4 x0 = __ldg(xp0 + t);
        float4 x1 = __ldg(xp1 + t);
        const int tp = min(t + PF_DIST, L0 - 1);
        prefetch_l1(xp0 + tp);
        prefetch_l1(xp1 + tp);

        // --- hh chains: start immediately from smem h, independent of x ---
        ull rhA = 0, zhA = 0, hn2a = bias_hn;
        ull rhB = 0, zhB = 0, hn2b = bias_hn;
        const ulonglong2* hpa = (const ulonglong2*)&hbuf[warp][p][0][0];
        const ulonglong2* hpb = (const ulonglong2*)&hbuf[warp][p][1][0];
        #pragma unroll
        for (int q = 0; q < H / 4; q++) {
            ulonglong2 ha = hpa[q];     // LDS.128 broadcast
            ulonglong2 hb = hpb[q];
            rhA  = fma2(Wr2[2*q],   ha.x, rhA);
            zhA  = fma2(Wz2[2*q],   ha.x, zhA);
            hn2a = fma2(Wn2[2*q],   ha.x, hn2a);
            rhB  = fma2(Wr2[2*q],   hb.x, rhB);
            zhB  = fma2(Wz2[2*q],   hb.x, zhB);
            hn2b = fma2(Wn2[2*q],   hb.x, hn2b);
            rhA  = fma2(Wr2[2*q+1], ha.y, rhA);
            zhA  = fma2(Wz2[2*q+1], ha.y, zhA);
            hn2a = fma2(Wn2[2*q+1], ha.y, hn2a);
            rhB  = fma2(Wr2[2*q+1], hb.y, rhB);
            zhB  = fma2(Wz2[2*q+1], hb.y, zhB);
            hn2b = fma2(Wn2[2*q+1], hb.y, hn2b);
        }

        // --- ih chains (x arrived during the matvec), seeded with biases ---
        const ull xa01 = pack2(x0.x, x0.y), xa23 = pack2(x0.z, x0.w);
        const ull xb01 = pack2(x1.x, x1.y), xb23 = pack2(x1.z, x1.w);
        ull riA = fma2(Wir23, xa23, fma2(Wir01, xa01, bias_r));
        ull ziA = fma2(Wiz23, xa23, fma2(Wiz01, xa01, bias_z));
        ull gnA = fma2(Win23, xa23, fma2(Win01, xa01, bias_in));
        ull riB = fma2(Wir23, xb23, fma2(Wir01, xb01, bias_r));
        ull ziB = fma2(Wiz23, xb23, fma2(Wiz01, xb01, bias_z));
        ull gnB = fma2(Win23, xb23, fma2(Win01, xb01, bias_in));

        // --- merge + activations (MUFU.TANH) ---
        float ra = fast_sigmoid(hsum2(add2(rhA, riA)));
        float rb = fast_sigmoid(hsum2(add2(rhB, riB)));
        float za = fast_sigmoid(hsum2(add2(zhA, ziA)));
        float zb = fast_sigmoid(hsum2(add2(zhB, ziB)));
        float na = mufu_tanh(fmaf(ra, hsum2(hn2a), hsum2(gnA)));
        float nb = mufu_tanh(fmaf(rb, hsum2(hn2b), hsum2(gnB)));
        h0 = fmaf(za, h0 - na, na);
        float h1n = fmaf(zb, h1 - nb, nb);
        h1 = (t < L1) ? h1n : h1;    // freeze shorter sequence past its length

        hbuf[warp][p ^ 1][0][lane] = h0;
        hbuf[warp][p ^ 1][1][lane] = h1;
        __syncwarp();
        p ^= 1;
    }

    g_hT[((size_t)b0 * F_FEAT + f) * H + lane] = h0;
    g_hT[((size_t)b1 * F_FEAT + f) * H + lane] = h1;
}

// Transpose W_sq [32][512] -> g_WT [512][32]
__global__ void transpose_wsq(const float* __restrict__ W_sq) {
    int i = blockIdx.x * blockDim.x + threadIdx.x;
    if (i < H * F_FEAT * H) {
        int r = i / (F_FEAT * H);
        int j = i % (F_FEAT * H);
        g_WT[j * H + r] = W_sq[i];
    }
}

// One warp per batch: h2 = relu(W_sq @ h_cat + b_sq); out = sigmoid(W_out @ h2 + b_out)
__global__ void head_kernel(
    const float* __restrict__ b_sq,
    const float* __restrict__ W_out,
    const float* __restrict__ b_out,
    float* __restrict__ out)
{
    const int lane = threadIdx.x & 31;
    const int b    = blockIdx.x * (blockDim.x >> 5) + (threadIdx.x >> 5);

    float acc = __ldg(b_sq + lane);
    const float* hb = g_hT + (size_t)b * (F_FEAT * H);

    for (int j0 = 0; j0 < F_FEAT * H; j0 += 32) {
        float hv = hb[j0 + lane];
        #pragma unroll
        for (int k = 0; k < 32; k++) {
            float hk = __shfl_sync(0xffffffffu, hv, k);
            acc = fmaf(g_WT[(j0 + k) * H + lane], hk, acc);
        }
    }

    float v = fmaxf(acc, 0.f) * __ldg(W_out + lane);
    #pragma unroll
    for (int off = 16; off; off >>= 1)
        v += __shfl_down_sync(0xffffffffu, v, off);

    if (lane == 0)
        out[b] = precise_sigmoid(v + __ldg(b_out));
}

extern "C" void kernel_launch(void* const* d_in, const int* in_sizes, int n_in,
                              void* d_out, int out_size) {
    const float* input = (const float*)d_in[0];
    const int*   lens  = (const int*)  d_in[1];
    const float* W_ih  = (const float*)d_in[2];
    const float* W_hh  = (const float*)d_in[3];
    const float* b_ih  = (const float*)d_in[4];
    const float* b_hh  = (const float*)d_in[5];
    const float* W_sq  = (const float*)d_in[6];
    const float* b_sq  = (const float*)d_in[7];
    const float* W_out = (const float*)d_in[8];
    const float* b_out = (const float*)d_in[9];
    float* out = (float*)d_out;

    sort_lens<<<(B_TOT + 255) / 256, 256>>>(lens);
    dim3 grid(B_TOT / 2, F_FEAT / 4);
    gru_kernel<<<grid, 128>>>(input, lens, W_ih, W_hh, b_ih, b_hh);
    transpose_wsq<<<(F_FEAT * H * H + 511) / 512, 512>>>(W_sq);
    head_kernel<<<B_TOT / 8, 256>>>(b_sq, W_out, b_out, out);
}

// round 12
// speedup vs baseline: 1.0042x; 1.0042x over previous
#include <cuda_runtime.h>
#include <cuda_bf16.h>

#define F_FEAT 16
#define D_IN   4
#define H      32
#define B_TOT  1024
#define T_MAX  512

typedef unsigned long long ull;

__device__ float g_hT[B_TOT * F_FEAT * H];      // [b][f][h]  == h_cat[b][f*H+h]
__device__ float g_WT[F_FEAT * H * H];          // W_sq transposed
__device__ int   g_perm[B_TOT];                 // batches sorted by len, descending

// HW tanh (MUFU.TANH): single op; verified end-to-end rel_err ~8e-8.
__device__ __forceinline__ float mufu_tanh(float x) {
    float y; asm("tanh.approx.f32 %0, %1;" : "=f"(y) : "f"(x)); return y;
}
__device__ __forceinline__ float fast_sigmoid(float v) {
    return fmaf(0.5f, mufu_tanh(0.5f * v), 0.5f);
}
__device__ __forceinline__ float precise_sigmoid(float v) {
    return __fdividef(1.f, 1.f + __expf(-v));
}
__device__ __forceinline__ ull pack2(float lo, float hi) {
    ull d; asm("mov.b64 %0, {%1, %2};" : "=l"(d) : "f"(lo), "f"(hi)); return d;
}
__device__ __forceinline__ void unpack2(ull v, float& lo, float& hi) {
    asm("mov.b64 {%0, %1}, %2;" : "=f"(lo), "=f"(hi) : "l"(v));
}
__device__ __forceinline__ ull fma2(ull a, ull b, ull c) {
    ull d; asm("fma.rn.f32x2 %0, %1, %2, %3;" : "=l"(d) : "l"(a), "l"(b), "l"(c)); return d;
}
__device__ __forceinline__ float hsum2(ull v) {
    float lo, hi; unpack2(v, lo, hi); return lo + hi;
}

// Rank-sort batches by length (descending, stable). O(B^2) but tiny (~5us).
__global__ void sort_lens(const int* __restrict__ lens) {
    int b = blockIdx.x * blockDim.x + threadIdx.x;
    if (b >= B_TOT) return;
    int L = lens[b];
    int r = 0;
    for (int j = 0; j < B_TOT; j++) {
        int Lj = __ldg(lens + j);
        r += (Lj < L) || (Lj == L && j < b);
    }
    g_perm[B_TOT - 1 - r] = b;   // descending: longest first
}

// One warp per (feature, batch-PAIR) — R9 structure (best known, 760us).
// Added: warp-phase stagger at entry. The 4 warps of a CTA run the same pair
// (same L, identical code) and otherwise convoy: all tails align and starve
// the FMA pipe. A one-time ~1/3-step offset per warp persists (equal step
// lengths) and interleaves one warp's matvec with another's serial tail.
__global__ void __launch_bounds__(128, 3) gru_kernel(
    const float* __restrict__ input,   // [B, F, T, D]
    const int*   __restrict__ lens,    // [B]
    const float* __restrict__ W_ih,    // [F, 3H, D]
    const float* __restrict__ W_hh,    // [F, 3H, H]
    const float* __restrict__ b_ih,    // [F, 3H]
    const float* __restrict__ b_hh)    // [F, 3H]
{
    __shared__ float hbuf[4][2][2][H];    // [warp][buffer][batch-slot][k]

    const int lane = threadIdx.x & 31;
    const int warp = threadIdx.x >> 5;
    const int pair = blockIdx.x;                 // 0..511, longest pairs first
    const int f    = blockIdx.y * 4 + warp;

    // de-convoy the 4 sibling warps (~1/3 step each; one-time cost < 1us total)
    if (warp) __nanosleep(warp * 128);

    const int b0 = __ldg(g_perm + 2 * pair);         // longer
    const int b1 = __ldg(g_perm + 2 * pair + 1);     // shorter (or equal)
    const int L0 = __ldg(lens + b0);                 // loop bound (max)
    const int L1 = __ldg(lens + b1);

    // --- recurrent weights, packed along k as (W[2q], W[2q+1]) pairs ---
    const float* Whh = W_hh + f * (3 * H) * H;
    ull Wr2[H/2], Wz2[H/2], Wn2[H/2];
    {
        const float4* r4 = (const float4*)(Whh + lane * H);
        const float4* z4 = (const float4*)(Whh + (H + lane) * H);
        const float4* n4 = (const float4*)(Whh + (2 * H + lane) * H);
        #pragma unroll
        for (int q = 0; q < H / 4; q++) {
            float4 a = __ldg(r4 + q);
            Wr2[2*q] = pack2(a.x, a.y);  Wr2[2*q+1] = pack2(a.z, a.w);
            float4 c = __ldg(z4 + q);
            Wz2[2*q] = pack2(c.x, c.y);  Wz2[2*q+1] = pack2(c.z, c.w);
            float4 d = __ldg(n4 + q);
            Wn2[2*q] = pack2(d.x, d.y);  Wn2[2*q+1] = pack2(d.z, d.w);
        }
    }

    // input weights, packed along d
    const float* Wih = W_ih + f * (3 * H) * D_IN;
    const float4 wir = __ldg((const float4*)Wih + lane);
    const float4 wiz = __ldg((const float4*)Wih + H + lane);
    const float4 win = __ldg((const float4*)Wih + 2 * H + lane);
    const ull Wir01 = pack2(wir.x, wir.y), Wir23 = pack2(wir.z, wir.w);
    const ull Wiz01 = pack2(wiz.x, wiz.y), Wiz23 = pack2(wiz.z, wiz.w);
    const ull Win01 = pack2(win.x, win.y), Win23 = pack2(win.z, win.w);

    const float br  = __ldg(b_ih + f * 3 * H + lane)     + __ldg(b_hh + f * 3 * H + lane);
    const float bz  = __ldg(b_ih + f * 3 * H + H + lane) + __ldg(b_hh + f * 3 * H + H + lane);
    const float bin = __ldg(b_ih + f * 3 * H + 2 * H + lane);
    const float bhn = __ldg(b_hh + f * 3 * H + 2 * H + lane);
    const ull  bias_r = pack2(br, 0.f), bias_z = pack2(bz, 0.f);
    const ull  bias_in = pack2(bin, 0.f), bias_hn = pack2(bhn, 0.f);

    const float4* xp0 = (const float4*)input + ((size_t)b0 * F_FEAT + f) * T_MAX;
    const float4* xp1 = (const float4*)input + ((size_t)b1 * F_FEAT + f) * T_MAX;

    float h0 = 0.f, h1 = 0.f;
    hbuf[warp][0][0][lane] = 0.f;
    hbuf[warp][0][1][lane] = 0.f;
    __syncwarp();
    int p = 0;

    float4 x0 = __ldg(xp0);          // L >= 1 always
    float4 x1 = __ldg(xp1);

    for (int t = 0; t < L0; t++) {
        // clamped t+1 preload into registers (R9 scheme — known good)
        const int tn = min(t + 1, L0 - 1);
        float4 xn0 = __ldg(xp0 + tn);
        float4 xn1 = __ldg(xp1 + tn);

        // input projections (pair-dots over d), both batches
        const ull xa01 = pack2(x0.x, x0.y), xa23 = pack2(x0.z, x0.w);
        const ull xb01 = pack2(x1.x, x1.y), xb23 = pack2(x1.z, x1.w);
        ull gr2a = fma2(Wir23, xa23, fma2(Wir01, xa01, bias_r));
        ull gz2a = fma2(Wiz23, xa23, fma2(Wiz01, xa01, bias_z));
        ull gn2a = fma2(Win23, xa23, fma2(Win01, xa01, bias_in));
        ull hn2a = bias_hn;
        ull gr2b = fma2(Wir23, xb23, fma2(Wir01, xb01, bias_r));
        ull gz2b = fma2(Wiz23, xb23, fma2(Wiz01, xb01, bias_z));
        ull gn2b = fma2(Win23, xb23, fma2(Win01, xb01, bias_in));
        ull hn2b = bias_hn;

        // recurrent matvecs: 6 independent fma2 chains over k
        const ulonglong2* hpa = (const ulonglong2*)&hbuf[warp][p][0][0];
        const ulonglong2* hpb = (const ulonglong2*)&hbuf[warp][p][1][0];
        #pragma unroll
        for (int q = 0; q < H / 4; q++) {
            ulonglong2 ha = hpa[q];     // LDS.128 broadcast
            ulonglong2 hb = hpb[q];
            gr2a = fma2(Wr2[2*q],   ha.x, gr2a);
            gz2a = fma2(Wz2[2*q],   ha.x, gz2a);
            hn2a = fma2(Wn2[2*q],   ha.x, hn2a);
            gr2b = fma2(Wr2[2*q],   hb.x, gr2b);
            gz2b = fma2(Wz2[2*q],   hb.x, gz2b);
            hn2b = fma2(Wn2[2*q],   hb.x, hn2b);
            gr2a = fma2(Wr2[2*q+1], ha.y, gr2a);
            gz2a = fma2(Wz2[2*q+1], ha.y, gz2a);
            hn2a = fma2(Wn2[2*q+1], ha.y, hn2a);
            gr2b = fma2(Wr2[2*q+1], hb.y, gr2b);
            gz2b = fma2(Wz2[2*q+1], hb.y, gz2b);
            hn2b = fma2(Wn2[2*q+1], hb.y, hn2b);
        }

        // activations via MUFU.TANH
        float ra = fast_sigmoid(hsum2(gr2a));
        float rb = fast_sigmoid(hsum2(gr2b));
        float za = fast_sigmoid(hsum2(gz2a));
        float zb = fast_sigmoid(hsum2(gz2b));
        float na = mufu_tanh(fmaf(ra, hsum2(hn2a), hsum2(gn2a)));
        float nb = mufu_tanh(fmaf(rb, hsum2(hn2b), hsum2(gn2b)));
        h0 = fmaf(za, h0 - na, na);
        float h1n = fmaf(zb, h1 - nb, nb);
        h1 = (t < L1) ? h1n : h1;    // freeze shorter sequence past its length

        hbuf[warp][p ^ 1][0][lane] = h0;
        hbuf[warp][p ^ 1][1][lane] = h1;
        __syncwarp();
        p ^= 1;
        x0 = xn0; x1 = xn1;
    }

    g_hT[((size_t)b0 * F_FEAT + f) * H + lane] = h0;
    g_hT[((size_t)b1 * F_FEAT + f) * H + lane] = h1;
}

// Transpose W_sq [32][512] -> g_WT [512][32]
__global__ void transpose_wsq(const float* __restrict__ W_sq) {
    int i = blockIdx.x * blockDim.x + threadIdx.x;
    if (i < H * F_FEAT * H) {
        int r = i / (F_FEAT * H);
        int j = i % (F_FEAT * H);
        g_WT[j * H + r] = W_sq[i];
    }
}

// One warp per batch: h2 = relu(W_sq @ h_cat + b_sq); out = sigmoid(W_out @ h2 + b_out)
__global__ void head_kernel(
    const float* __restrict__ b_sq,
    const float* __restrict__ W_out,
    const float* __restrict__ b_out,
    float* __restrict__ out)
{
    const int lane = threadIdx.x & 31;
    const int b    = blockIdx.x * (blockDim.x >> 5) + (threadIdx.x >> 5);

    float acc = __ldg(b_sq + lane);
    const float* hb = g_hT + (size_t)b * (F_FEAT * H);

    for (int j0 = 0; j0 < F_FEAT * H; j0 += 32) {
        float hv = hb[j0 + lane];
        #pragma unroll
        for (int k = 0; k < 32; k++) {
            float hk = __shfl_sync(0xffffffffu, hv, k);
            acc = fmaf(g_WT[(j0 + k) * H + lane], hk, acc);
        }
    }

    float v = fmaxf(acc, 0.f) * __ldg(W_out + lane);
    #pragma unroll
    for (int off = 16; off; off >>= 1)
        v += __shfl_down_sync(0xffffffffu, v, off);

    if (lane == 0)
        out[b] = precise_sigmoid(v + __ldg(b_out));
}

extern "C" void kernel_launch(void* const* d_in, const int* in_sizes, int n_in,
                              void* d_out, int out_size) {
    const float* input = (const float*)d_in[0];
    const int*   lens  = (const int*)  d_in[1];
    const float* W_ih  = (const float*)d_in[2];
    const float* W_hh  = (const float*)d_in[3];
    const float* b_ih  = (const float*)d_in[4];
    const float* b_hh  = (const float*)d_in[5];
    const float* W_sq  = (const float*)d_in[6];
    const float* b_sq  = (const float*)d_in[7];
    const float* W_out = (const float*)d_in[8];
    const float* b_out = (const float*)d_in[9];
    float* out = (float*)d_out;

    // Launch order puts gru_kernel at stream index 3 so the fixed ncu window
    // (-s 5 -c 1 => 4th kernel) finally profiles the hot kernel. The duplicate
    // transpose is idempotent and ~2us. All dependencies respected:
    // sort(1) before gru(3); transpose(0,2) before head(4); gru before head.
    transpose_wsq<<<(F_FEAT * H * H + 511) / 512, 512>>>(W_sq);
    sort_lens<<<(B_TOT + 255) / 256, 256>>>(lens);
    transpose_wsq<<<(F_FEAT * H * H + 511) / 512, 512>>>(W_sq);
    dim3 grid(B_TOT / 2, F_FEAT / 4);
    gru_kernel<<<grid, 128>>>(input, lens, W_ih, W_hh, b_ih, b_hh);
    head_kernel<<<B_TOT / 8, 256>>>(b_sq, W_out, b_out, out);
}

// round 15
// speedup vs baseline: 1.0099x; 1.0057x over previous
#include <cuda_runtime.h>
#include <cuda_bf16.h>

#define F_FEAT 16
#define D_IN   4
#define H      32
#define B_TOT  1024
#define T_MAX  512

__device__ float g_hT[B_TOT * F_FEAT * H];      // [b][f][h]  == h_cat[b][f*H+h]
__device__ float g_WT[F_FEAT * H * H];          // W_sq transposed
__device__ int   g_perm[B_TOT];                 // batches sorted by len, descending

// HW tanh (MUFU.TANH): single op; verified end-to-end rel_err ~8e-8.
__device__ __forceinline__ float mufu_tanh(float x) {
    float y; asm("tanh.approx.f32 %0, %1;" : "=f"(y) : "f"(x)); return y;
}
__device__ __forceinline__ float fast_sigmoid(float v) {
    return fmaf(0.5f, mufu_tanh(0.5f * v), 0.5f);
}
__device__ __forceinline__ float precise_sigmoid(float v) {
    return __fdividef(1.f, 1.f + __expf(-v));
}

// Rank-sort batches by length (descending, stable). O(B^2) but tiny (~5us).
__global__ void sort_lens(const int* __restrict__ lens) {
    int b = blockIdx.x * blockDim.x + threadIdx.x;
    if (b >= B_TOT) return;
    int L = lens[b];
    int r = 0;
    for (int j = 0; j < B_TOT; j++) {
        int Lj = __ldg(lens + j);
        r += (Lj < L) || (Lj == L && j < b);
    }
    g_perm[B_TOT - 1 - r] = b;   // descending: longest first
}

// One warp per (feature, batch-PAIR). Pure scalar FFMA version:
// fma.rn.f32x2 measured as throughput-neutral on sm_100a (fma-busy time
// invariant across R1/R2/R12), so the pack/unpack/alignment overhead it
// carries is pure waste. Scalar accumulators also eliminate all hsums.
__global__ void __launch_bounds__(128, 3) gru_kernel(
    const float* __restrict__ input,   // [B, F, T, D]
    const int*   __restrict__ lens,    // [B]
    const float* __restrict__ W_ih,    // [F, 3H, D]
    const float* __restrict__ W_hh,    // [F, 3H, H]
    const float* __restrict__ b_ih,    // [F, 3H]
    const float* __restrict__ b_hh)    // [F, 3H]
{
    __shared__ float hbuf[4][2][2][H];    // [warp][buffer][batch-slot][k]

    const int lane = threadIdx.x & 31;
    const int warp = threadIdx.x >> 5;
    const int pair = blockIdx.x;                 // 0..511, longest pairs first
    const int f    = blockIdx.y * 4 + warp;

    const int b0 = __ldg(g_perm + 2 * pair);         // longer
    const int b1 = __ldg(g_perm + 2 * pair + 1);     // shorter (or equal)
    const int L0 = __ldg(lens + b0);                 // loop bound (max)
    const int L1 = __ldg(lens + b1);

    // --- recurrent weights in registers, scalar form (96 floats) ---
    const float* Whh = W_hh + f * (3 * H) * H;
    float Wr[H], Wz[H], Wn[H];
    {
        const float4* r4 = (const float4*)(Whh + lane * H);
        const float4* z4 = (const float4*)(Whh + (H + lane) * H);
        const float4* n4 = (const float4*)(Whh + (2 * H + lane) * H);
        #pragma unroll
        for (int q = 0; q < H / 4; q++) {
            float4 a = __ldg(r4 + q);
            Wr[4*q] = a.x; Wr[4*q+1] = a.y; Wr[4*q+2] = a.z; Wr[4*q+3] = a.w;
            float4 c = __ldg(z4 + q);
            Wz[4*q] = c.x; Wz[4*q+1] = c.y; Wz[4*q+2] = c.z; Wz[4*q+3] = c.w;
            float4 d = __ldg(n4 + q);
            Wn[4*q] = d.x; Wn[4*q+1] = d.y; Wn[4*q+2] = d.z; Wn[4*q+3] = d.w;
        }
    }

    // input weights
    const float* Wih = W_ih + f * (3 * H) * D_IN;
    const float4 wir = __ldg((const float4*)Wih + lane);
    const float4 wiz = __ldg((const float4*)Wih + H + lane);
    const float4 win = __ldg((const float4*)Wih + 2 * H + lane);

    const float br  = __ldg(b_ih + f * 3 * H + lane)     + __ldg(b_hh + f * 3 * H + lane);
    const float bz  = __ldg(b_ih + f * 3 * H + H + lane) + __ldg(b_hh + f * 3 * H + H + lane);
    const float bin = __ldg(b_ih + f * 3 * H + 2 * H + lane);
    const float bhn = __ldg(b_hh + f * 3 * H + 2 * H + lane);

    const float4* xp0 = (const float4*)input + ((size_t)b0 * F_FEAT + f) * T_MAX;
    const float4* xp1 = (const float4*)input + ((size_t)b1 * F_FEAT + f) * T_MAX;

    float h0 = 0.f, h1 = 0.f;
    hbuf[warp][0][0][lane] = 0.f;
    hbuf[warp][0][1][lane] = 0.f;
    __syncwarp();
    int p = 0;

    float4 x0 = __ldg(xp0);          // L >= 1 always
    float4 x1 = __ldg(xp1);

    for (int t = 0; t < L0; t++) {
        // clamped t+1 preload into registers (known good)
        const int tn = min(t + 1, L0 - 1);
        float4 xn0 = __ldg(xp0 + tn);
        float4 xn1 = __ldg(xp1 + tn);

        // input projections, scalar fmaf chains seeded with fused biases
        float gra = fmaf(x0.w, wir.w, fmaf(x0.z, wir.z, fmaf(x0.y, wir.y, fmaf(x0.x, wir.x, br))));
        float gza = fmaf(x0.w, wiz.w, fmaf(x0.z, wiz.z, fmaf(x0.y, wiz.y, fmaf(x0.x, wiz.x, bz))));
        float gna = fmaf(x0.w, win.w, fmaf(x0.z, win.z, fmaf(x0.y, win.y, fmaf(x0.x, win.x, bin))));
        float hna = bhn;
        float grb = fmaf(x1.w, wir.w, fmaf(x1.z, wir.z, fmaf(x1.y, wir.y, fmaf(x1.x, wir.x, br))));
        float gzb = fmaf(x1.w, wiz.w, fmaf(x1.z, wiz.z, fmaf(x1.y, wiz.y, fmaf(x1.x, wiz.x, bz))));
        float gnb = fmaf(x1.w, win.w, fmaf(x1.z, win.z, fmaf(x1.y, win.y, fmaf(x1.x, win.x, bin))));
        float hnb = bhn;

        // recurrent matvecs: scalar FFMA, 8 independent accumulator chains
        const float4* hpa = (const float4*)&hbuf[warp][p][0][0];
        const float4* hpb = (const float4*)&hbuf[warp][p][1][0];
        #pragma unroll
        for (int q = 0; q < H / 4; q++) {
            float4 ha = hpa[q];     // LDS.128 broadcast
            float4 hb = hpb[q];
            gra = fmaf(Wr[4*q],   ha.x, gra);
            gza = fmaf(Wz[4*q],   ha.x, gza);
            hna = fmaf(Wn[4*q],   ha.x, hna);
            grb = fmaf(Wr[4*q],   hb.x, grb);
            gzb = fmaf(Wz[4*q],   hb.x, gzb);
            hnb = fmaf(Wn[4*q],   hb.x, hnb);
            gra = fmaf(Wr[4*q+1], ha.y, gra);
            gza = fmaf(Wz[4*q+1], ha.y, gza);
            hna = fmaf(Wn[4*q+1], ha.y, hna);
            grb = fmaf(Wr[4*q+1], hb.y, grb);
            gzb = fmaf(Wz[4*q+1], hb.y, gzb);
            hnb = fmaf(Wn[4*q+1], hb.y, hnb);
            gra = fmaf(Wr[4*q+2], ha.z, gra);
            gza = fmaf(Wz[4*q+2], ha.z, gza);
            hna = fmaf(Wn[4*q+2], ha.z, hna);
            grb = fmaf(Wr[4*q+2], hb.z, grb);
            gzb = fmaf(Wz[4*q+2], hb.z, gzb);
            hnb = fmaf(Wn[4*q+2], hb.z, hnb);
            gra = fmaf(Wr[4*q+3], ha.w, gra);
            gza = fmaf(Wz[4*q+3], ha.w, gza);
            hna = fmaf(Wn[4*q+3], ha.w, hna);
            grb = fmaf(Wr[4*q+3], hb.w, grb);
            gzb = fmaf(Wz[4*q+3], hb.w, gzb);
            hnb = fmaf(Wn[4*q+3], hb.w, hnb);
        }

        // activations via MUFU.TANH (no hsums needed — accumulators are scalar)
        float ra = fast_sigmoid(gra);
        float rb = fast_sigmoid(grb);
        float za = fast_sigmoid(gza);
        float zb = fast_sigmoid(gzb);
        float na = mufu_tanh(fmaf(ra, hna, gna));
        float nb = mufu_tanh(fmaf(rb, hnb, gnb));
        h0 = fmaf(za, h0 - na, na);
        float h1n = fmaf(zb, h1 - nb, nb);
        h1 = (t < L1) ? h1n : h1;    // freeze shorter sequence past its length

        hbuf[warp][p ^ 1][0][lane] = h0;
        hbuf[warp][p ^ 1][1][lane] = h1;
        __syncwarp();
        p ^= 1;
        x0 = xn0; x1 = xn1;
    }

    g_hT[((size_t)b0 * F_FEAT + f) * H + lane] = h0;
    g_hT[((size_t)b1 * F_FEAT + f) * H + lane] = h1;
}

// Transpose W_sq [32][512] -> g_WT [512][32]
__global__ void transpose_wsq(const float* __restrict__ W_sq) {
    int i = blockIdx.x * blockDim.x + threadIdx.x;
    if (i < H * F_FEAT * H) {
        int r = i / (F_FEAT * H);
        int j = i % (F_FEAT * H);
        g_WT[j * H + r] = W_sq[i];
    }
}

// One warp per batch: h2 = relu(W_sq @ h_cat + b_sq); out = sigmoid(W_out @ h2 + b_out)
__global__ void head_kernel(
    const float* __restrict__ b_sq,
    const float* __restrict__ W_out,
    const float* __restrict__ b_out,
    float* __restrict__ out)
{
    const int lane = threadIdx.x & 31;
    const int b    = blockIdx.x * (blockDim.x >> 5) + (threadIdx.x >> 5);

    float acc = __ldg(b_sq + lane);
    const float* hb = g_hT + (size_t)b * (F_FEAT * H);

    for (int j0 = 0; j0 < F_FEAT * H; j0 += 32) {
        float hv = hb[j0 + lane];
        #pragma unroll
        for (int k = 0; k < 32; k++) {
            float hk = __shfl_sync(0xffffffffu, hv, k);
            acc = fmaf(g_WT[(j0 + k) * H + lane], hk, acc);
        }
    }

    float v = fmaxf(acc, 0.f) * __ldg(W_out + lane);
    #pragma unroll
    for (int off = 16; off; off >>= 1)
        v += __shfl_down_sync(0xffffffffu, v, off);

    if (lane == 0)
        out[b] = precise_sigmoid(v + __ldg(b_out));
}

extern "C" void kernel_launch(void* const* d_in, const int* in_sizes, int n_in,
                              void* d_out, int out_size) {
    const float* input = (const float*)d_in[0];
    const int*   lens  = (const int*)  d_in[1];
    const float* W_ih  = (const float*)d_in[2];
    const float* W_hh  = (const float*)d_in[3];
    const float* b_ih  = (const float*)d_in[4];
    const float* b_hh  = (const float*)d_in[5];
    const float* W_sq  = (const float*)d_in[6];
    const float* b_sq  = (const float*)d_in[7];
    const float* W_out = (const float*)d_in[8];
    const float* b_out = (const float*)d_in[9];
    float* out = (float*)d_out;

    // gru_kernel kept at stream index 3 so the fixed ncu window (-s 5 -c 1)
    // profiles the hot kernel. Duplicate transpose is idempotent, ~2us.
    transpose_wsq<<<(F_FEAT * H * H + 511) / 512, 512>>>(W_sq);
    sort_lens<<<(B_TOT + 255) / 256, 256>>>(lens);
    transpose_wsq<<<(F_FEAT * H * H + 511) / 512, 512>>>(W_sq);
    dim3 grid(B_TOT / 2, F_FEAT / 4);
    gru_kernel<<<grid, 128>>>(input, lens, W_ih, W_hh, b_ih, b_hh);
    head_kernel<<<B_TOT / 8, 256>>>(b_sq, W_out, b_out, out);
}

// round 16
// speedup vs baseline: 1.0287x; 1.0186x over previous
#include <cuda_runtime.h>
#include <cuda_bf16.h>

#define F_FEAT 16
#define D_IN   4
#define H      32
#define B_TOT  1024
#define T_MAX  512

__device__ float g_hT[B_TOT * F_FEAT * H];      // [b][f][h]  == h_cat[b][f*H+h]
__device__ float g_WT[F_FEAT * H * H];          // W_sq transposed
__device__ int   g_perm[B_TOT];                 // batches sorted by len, descending

// HW tanh (MUFU.TANH): single op; verified end-to-end rel_err ~8e-8.
__device__ __forceinline__ float mufu_tanh(float x) {
    float y; asm("tanh.approx.f32 %0, %1;" : "=f"(y) : "f"(x)); return y;
}
__device__ __forceinline__ float fast_sigmoid(float v) {
    return fmaf(0.5f, mufu_tanh(0.5f * v), 0.5f);
}
__device__ __forceinline__ float precise_sigmoid(float v) {
    return __fdividef(1.f, 1.f + __expf(-v));
}

// Rank-sort batches by length (descending, stable). O(B^2) but tiny (~5us).
__global__ void sort_lens(const int* __restrict__ lens) {
    int b = blockIdx.x * blockDim.x + threadIdx.x;
    if (b >= B_TOT) return;
    int L = lens[b];
    int r = 0;
    for (int j = 0; j < B_TOT; j++) {
        int Lj = __ldg(lens + j);
        r += (Lj < L) || (Lj == L && j < b);
    }
    g_perm[B_TOT - 1 - r] = b;   // descending: longest first
}

// One warp per (feature, batch-PAIR), scalar FFMA (R15 base, issue=72.9%).
// NEW: software-pipelined input projection — ih(t+1) is computed AFTER the
// matvec of step t, so its 24 independent FMAs fill the MUFU/h-update/sync
// tail where the warp previously had nothing to issue. x registers are no
// longer carried across iterations (only 6 ih scalars), so regs drop.
__global__ void __launch_bounds__(128, 3) gru_kernel(
    const float* __restrict__ input,   // [B, F, T, D]
    const int*   __restrict__ lens,    // [B]
    const float* __restrict__ W_ih,    // [F, 3H, D]
    const float* __restrict__ W_hh,    // [F, 3H, H]
    const float* __restrict__ b_ih,    // [F, 3H]
    const float* __restrict__ b_hh)    // [F, 3H]
{
    __shared__ float hbuf[4][2][2][H];    // [warp][buffer][batch-slot][k]

    const int lane = threadIdx.x & 31;
    const int warp = threadIdx.x >> 5;
    const int pair = blockIdx.x;                 // 0..511, longest pairs first
    const int f    = blockIdx.y * 4 + warp;

    const int b0 = __ldg(g_perm + 2 * pair);         // longer
    const int b1 = __ldg(g_perm + 2 * pair + 1);     // shorter (or equal)
    const int L0 = __ldg(lens + b0);                 // loop bound (max)
    const int L1 = __ldg(lens + b1);

    // --- recurrent weights in registers, scalar form (96 floats) ---
    const float* Whh = W_hh + f * (3 * H) * H;
    float Wr[H], Wz[H], Wn[H];
    {
        const float4* r4 = (const float4*)(Whh + lane * H);
        const float4* z4 = (const float4*)(Whh + (H + lane) * H);
        const float4* n4 = (const float4*)(Whh + (2 * H + lane) * H);
        #pragma unroll
        for (int q = 0; q < H / 4; q++) {
            float4 a = __ldg(r4 + q);
            Wr[4*q] = a.x; Wr[4*q+1] = a.y; Wr[4*q+2] = a.z; Wr[4*q+3] = a.w;
            float4 c = __ldg(z4 + q);
            Wz[4*q] = c.x; Wz[4*q+1] = c.y; Wz[4*q+2] = c.z; Wz[4*q+3] = c.w;
            float4 d = __ldg(n4 + q);
            Wn[4*q] = d.x; Wn[4*q+1] = d.y; Wn[4*q+2] = d.z; Wn[4*q+3] = d.w;
        }
    }

    // input weights
    const float* Wih = W_ih + f * (3 * H) * D_IN;
    const float4 wir = __ldg((const float4*)Wih + lane);
    const float4 wiz = __ldg((const float4*)Wih + H + lane);
    const float4 win = __ldg((const float4*)Wih + 2 * H + lane);

    const float br  = __ldg(b_ih + f * 3 * H + lane)     + __ldg(b_hh + f * 3 * H + lane);
    const float bz  = __ldg(b_ih + f * 3 * H + H + lane) + __ldg(b_hh + f * 3 * H + H + lane);
    const float bin = __ldg(b_ih + f * 3 * H + 2 * H + lane);
    const float bhn = __ldg(b_hh + f * 3 * H + 2 * H + lane);

    const float4* xp0 = (const float4*)input + ((size_t)b0 * F_FEAT + f) * T_MAX;
    const float4* xp1 = (const float4*)input + ((size_t)b1 * F_FEAT + f) * T_MAX;

    float h0 = 0.f, h1 = 0.f;
    hbuf[warp][0][0][lane] = 0.f;
    hbuf[warp][0][1][lane] = 0.f;
    __syncwarp();
    int p = 0;

    // prologue: ih projection for t=0 (L >= 1 always)
    float ihra, ihza, ihna, ihrb, ihzb, ihnb;
    {
        float4 x0 = __ldg(xp0);
        float4 x1 = __ldg(xp1);
        ihra = fmaf(x0.w, wir.w, fmaf(x0.z, wir.z, fmaf(x0.y, wir.y, fmaf(x0.x, wir.x, br))));
        ihza = fmaf(x0.w, wiz.w, fmaf(x0.z, wiz.z, fmaf(x0.y, wiz.y, fmaf(x0.x, wiz.x, bz))));
        ihna = fmaf(x0.w, win.w, fmaf(x0.z, win.z, fmaf(x0.y, win.y, fmaf(x0.x, win.x, bin))));
        ihrb = fmaf(x1.w, wir.w, fmaf(x1.z, wir.z, fmaf(x1.y, wir.y, fmaf(x1.x, wir.x, br))));
        ihzb = fmaf(x1.w, wiz.w, fmaf(x1.z, wiz.z, fmaf(x1.y, wiz.y, fmaf(x1.x, wiz.x, bz))));
        ihnb = fmaf(x1.w, win.w, fmaf(x1.z, win.z, fmaf(x1.y, win.y, fmaf(x1.x, win.x, bin))));
    }

    for (int t = 0; t < L0; t++) {
        // x for step t+1 (clamped duplicate at the end is never consumed)
        const int tn = min(t + 1, L0 - 1);
        float4 xn0 = __ldg(xp0 + tn);
        float4 xn1 = __ldg(xp1 + tn);

        // seed accumulators from the PRE-COMPUTED ih projection of step t
        float gra = ihra, gza = ihza, gna = ihna, hna = bhn;
        float grb = ihrb, gzb = ihzb, gnb = ihnb, hnb = bhn;

        // recurrent matvecs: scalar FFMA, 8 independent accumulator chains
        const float4* hpa = (const float4*)&hbuf[warp][p][0][0];
        const float4* hpb = (const float4*)&hbuf[warp][p][1][0];
        #pragma unroll
        for (int q = 0; q < H / 4; q++) {
            float4 ha = hpa[q];     // LDS.128 broadcast
            float4 hb = hpb[q];
            gra = fmaf(Wr[4*q],   ha.x, gra);
            gza = fmaf(Wz[4*q],   ha.x, gza);
            hna = fmaf(Wn[4*q],   ha.x, hna);
            grb = fmaf(Wr[4*q],   hb.x, grb);
            gzb = fmaf(Wz[4*q],   hb.x, gzb);
            hnb = fmaf(Wn[4*q],   hb.x, hnb);
            gra = fmaf(Wr[4*q+1], ha.y, gra);
            gza = fmaf(Wz[4*q+1], ha.y, gza);
            hna = fmaf(Wn[4*q+1], ha.y, hna);
            grb = fmaf(Wr[4*q+1], hb.y, grb);
            gzb = fmaf(Wz[4*q+1], hb.y, gzb);
            hnb = fmaf(Wn[4*q+1], hb.y, hnb);
            gra = fmaf(Wr[4*q+2], ha.z, gra);
            gza = fmaf(Wz[4*q+2], ha.z, gza);
            hna = fmaf(Wn[4*q+2], ha.z, hna);
            grb = fmaf(Wr[4*q+2], hb.z, grb);
            gzb = fmaf(Wz[4*q+2], hb.z, gzb);
            hnb = fmaf(Wn[4*q+2], hb.z, hnb);
            gra = fmaf(Wr[4*q+3], ha.w, gra);
            gza = fmaf(Wz[4*q+3], ha.w, gza);
            hna = fmaf(Wn[4*q+3], ha.w, hna);
            grb = fmaf(Wr[4*q+3], hb.w, grb);
            gzb = fmaf(Wz[4*q+3], hb.w, gzb);
            hnb = fmaf(Wn[4*q+3], hb.w, hnb);
        }

        // ih projection for step t+1 — fully independent of this step's
        // recurrence; these 24 FMAs fill the MUFU/update/sync tail below.
        ihra = fmaf(xn0.w, wir.w, fmaf(xn0.z, wir.z, fmaf(xn0.y, wir.y, fmaf(xn0.x, wir.x, br))));
        ihza = fmaf(xn0.w, wiz.w, fmaf(xn0.z, wiz.z, fmaf(xn0.y, wiz.y, fmaf(xn0.x, wiz.x, bz))));
        ihna = fmaf(xn0.w, win.w, fmaf(xn0.z, win.z, fmaf(xn0.y, win.y, fmaf(xn0.x, win.x, bin))));
        ihrb = fmaf(xn1.w, wir.w, fmaf(xn1.z, wir.z, fmaf(xn1.y, wir.y, fmaf(xn1.x, wir.x, br))));
        ihzb = fmaf(xn1.w, wiz.w, fmaf(xn1.z, wiz.z, fmaf(xn1.y, wiz.y, fmaf(xn1.x, wiz.x, bz))));
        ihnb = fmaf(xn1.w, win.w, fmaf(xn1.z, win.z, fmaf(xn1.y, win.y, fmaf(xn1.x, win.x, bin))));

        // activations via MUFU.TANH
        float ra = fast_sigmoid(gra);
        float rb = fast_sigmoid(grb);
        float za = fast_sigmoid(gza);
        float zb = fast_sigmoid(gzb);
        float na = mufu_tanh(fmaf(ra, hna, gna));
        float nb = mufu_tanh(fmaf(rb, hnb, gnb));
        h0 = fmaf(za, h0 - na, na);
        float h1n = fmaf(zb, h1 - nb, nb);
        h1 = (t < L1) ? h1n : h1;    // freeze shorter sequence past its length

        hbuf[warp][p ^ 1][0][lane] = h0;
        hbuf[warp][p ^ 1][1][lane] = h1;
        __syncwarp();
        p ^= 1;
    }

    g_hT[((size_t)b0 * F_FEAT + f) * H + lane] = h0;
    g_hT[((size_t)b1 * F_FEAT + f) * H + lane] = h1;
}

// Transpose W_sq [32][512] -> g_WT [512][32]
__global__ void transpose_wsq(const float* __restrict__ W_sq) {
    int i = blockIdx.x * blockDim.x + threadIdx.x;
    if (i < H * F_FEAT * H) {
        int r = i / (F_FEAT * H);
        int j = i % (F_FEAT * H);
        g_WT[j * H + r] = W_sq[i];
    }
}

// One warp per batch: h2 = relu(W_sq @ h_cat + b_sq); out = sigmoid(W_out @ h2 + b_out)
__global__ void head_kernel(
    const float* __restrict__ b_sq,
    const float* __restrict__ W_out,
    const float* __restrict__ b_out,
    float* __restrict__ out)
{
    const int lane = threadIdx.x & 31;
    const int b    = blockIdx.x * (blockDim.x >> 5) + (threadIdx.x >> 5);

    float acc = __ldg(b_sq + lane);
    const float* hb = g_hT + (size_t)b * (F_FEAT * H);

    for (int j0 = 0; j0 < F_FEAT * H; j0 += 32) {
        float hv = hb[j0 + lane];
        #pragma unroll
        for (int k = 0; k < 32; k++) {
            float hk = __shfl_sync(0xffffffffu, hv, k);
            acc = fmaf(g_WT[(j0 + k) * H + lane], hk, acc);
        }
    }

    float v = fmaxf(acc, 0.f) * __ldg(W_out + lane);
    #pragma unroll
    for (int off = 16; off; off >>= 1)
        v += __shfl_down_sync(0xffffffffu, v, off);

    if (lane == 0)
        out[b] = precise_sigmoid(v + __ldg(b_out));
}

extern "C" void kernel_launch(void* const* d_in, const int* in_sizes, int n_in,
                              void* d_out, int out_size) {
    const float* input = (const float*)d_in[0];
    const int*   lens  = (const int*)  d_in[1];
    const float* W_ih  = (const float*)d_in[2];
    const float* W_hh  = (const float*)d_in[3];
    const float* b_ih  = (const float*)d_in[4];
    const float* b_hh  = (const float*)d_in[5];
    const float* W_sq  = (const float*)d_in[6];
    const float* b_sq  = (const float*)d_in[7];
    const float* W_out = (const float*)d_in[8];
    const float* b_out = (const float*)d_in[9];
    float* out = (float*)d_out;

    // gru_kernel kept at stream index 3 so the fixed ncu window (-s 5 -c 1)
    // profiles the hot kernel. Duplicate transpose is idempotent, ~2us.
    transpose_wsq<<<(F_FEAT * H * H + 511) / 512, 512>>>(W_sq);
    sort_lens<<<(B_TOT + 255) / 256, 256>>>(lens);
    transpose_wsq<<<(F_FEAT * H * H + 511) / 512, 512>>>(W_sq);
    dim3 grid(B_TOT / 2, F_FEAT / 4);
    gru_kernel<<<grid, 128>>>(input, lens, W_ih, W_hh, b_ih, b_hh);
    head_kernel<<<B_TOT / 8, 256>>>(b_sq, W_out, b_out, out);
}